// round 17
// baseline (speedup 1.0000x reference)
#include <cuda_runtime.h>
#include <math.h>

// B=16, M=N=256, C=OUT=64, modes=32/axis, FF_HID=256.
#define PI_D 3.14159265358979323846
typedef unsigned long long u64;

__device__ __forceinline__ u64 pack2(float lo, float hi) {
    u64 r; asm("mov.b64 %0,{%1,%2};" : "=l"(r) : "f"(lo), "f"(hi)); return r;
}
__device__ __forceinline__ float2 unpk(u64 v) {
    float2 f; asm("mov.b64 {%0,%1},%2;" : "=f"(f.x), "=f"(f.y) : "l"(v)); return f;
}
__device__ __forceinline__ void fma2(u64& d, u64 a, u64 b) {
    asm("fma.rn.f32x2 %0,%1,%2,%0;" : "+l"(d) : "l"(a), "l"(b));
}

// ----------------------------- device scratch ------------------------------
__device__ float g_Ft [256 * 64];            // forward DFT [n][kr]
__device__ float g_Cit[256 * 64];            // inverse DFT [n][kr]
__device__ float g_w1t[2 * 32 * 64 * 64];
__device__ float g_w2t[2 * 32 * 64 * 64];
__device__ float g_S [(size_t)4096 * 4096];  // y-path spectra
__device__ float g_S2[(size_t)4096 * 4096];  // x-path spectra
__device__ float g_T [(size_t)4096 * 4096];
__device__ float g_T2[(size_t)4096 * 4096];
__device__ float g_Z[(size_t)1048576 * 64];

// ----------------------------- basis ---------------------------------------
__global__ void k_basis() {
    int idx = blockIdx.x * 256 + threadIdx.x;
    if (idx >= 16384) return;
    int n = idx >> 6, kr = idx & 63, k = kr >> 1;
    double th = 2.0 * PI_D * (double)k * (double)n / 256.0;
    double c = cos(th), s = sin(th);
    g_Ft[idx] = (float)(((kr & 1) ? -s : c) * 0.0625);
    double v;
    if (k == 0) v = (kr & 1) ? 0.0 : 0.0625;
    else        v = ((kr & 1) ? -2.0 * s : 2.0 * c) * 0.0625;
    g_Cit[idx] = (float)v;
}

__global__ void k_wt(const float* __restrict__ w1re, const float* __restrict__ w1im,
                     const float* __restrict__ w2re, const float* __restrict__ w2im) {
    int idx = blockIdx.x * 256 + threadIdx.x;
    if (idx >= 131072) return;
    int k = idx >> 12, c = (idx >> 6) & 63, o = idx & 63;
    int src = (c * 64 + o) * 32 + k;
    g_w1t[idx]          = w1re[src];
    g_w1t[131072 + idx] = w1im[src];
    g_w2t[idx]          = w2re[src];
    g_w2t[131072 + idx] = w2im[src];
}

// --------------------- forward DFT GEMM, both paths, 4 slabs/block ----------
// S[slab][kr][c] = sum_n Ft[n][kr] * x[slab][n][c]. 8kr x 8c tiles.
__global__ __launch_bounds__(256, 2) void k_fwd(const float* __restrict__ x) {
    extern __shared__ float sm[];
    float* fs = sm;          // [32][64]
    float* xs = sm + 2048;   // [4][32][64]
    int t = threadIdx.x;
    int path = blockIdx.x >> 10;
    int slab0 = (blockIdx.x & 1023) * 4;
    int s1 = t >> 6, tx = t & 7, ty = (t >> 3) & 7;

    u64 acc[4][8] = {};   // [kr-pair][c]

    for (int h = 0; h < 8; h++) {
        for (int i = t; i < 512; i += 256)
            ((float4*)fs)[i] = ((const float4*)g_Ft)[h * 512 + i];
        if (!path) {
            for (int i = t; i < 2048; i += 256) {
                int ssl = i >> 9, j = i & 511;
                ((float4*)xs)[i] =
                    ((const float4*)x)[(size_t)(slab0 + ssl) * 4096u + (size_t)h * 512u + j];
            }
        } else {
            for (int i = t; i < 2048; i += 256) {
                int ssl = i >> 9, j = i & 511;
                int nn = j >> 4, c4 = (j & 15) * 4;
                int slab = slab0 + ssl;
                size_t base = (size_t)(slab >> 8) * 4194304u + (size_t)(slab & 255) * 64u;
                ((float4*)xs)[i] = *(const float4*)(x + base + (size_t)(h * 32 + nn) * 16384u + c4);
            }
        }
        __syncthreads();

        const float* fb = fs + ty * 8;
        const float* xb = xs + s1 * 2048 + tx * 8;
#pragma unroll 4
        for (int n = 0; n < 32; n++) {
            ulonglong2 fA = *(const ulonglong2*)(fb + n * 64);      // kr pairs 0-3
            ulonglong2 fB = *(const ulonglong2*)(fb + n * 64 + 4);  // kr pairs 4-7
            float4 x0 = *(const float4*)(xb + n * 64);
            float4 x1 = *(const float4*)(xb + n * 64 + 4);
            u64 xq[8] = {pack2(x0.x, x0.x), pack2(x0.y, x0.y), pack2(x0.z, x0.z), pack2(x0.w, x0.w),
                         pack2(x1.x, x1.x), pack2(x1.y, x1.y), pack2(x1.z, x1.z), pack2(x1.w, x1.w)};
#pragma unroll
            for (int cc = 0; cc < 8; cc++) {
                fma2(acc[0][cc], fA.x, xq[cc]);
                fma2(acc[1][cc], fA.y, xq[cc]);
                fma2(acc[2][cc], fB.x, xq[cc]);
                fma2(acc[3][cc], fB.y, xq[cc]);
            }
        }
        __syncthreads();
    }

    float* Sd = (path ? g_S2 : g_S) + (size_t)(slab0 + s1) * 4096u
              + (size_t)(ty * 8) * 64u + tx * 8;
#pragma unroll
    for (int p = 0; p < 4; p++) {
        float2 a[8];
#pragma unroll
        for (int cc = 0; cc < 8; cc++) a[cc] = unpk(acc[p][cc]);
        float* pe = Sd + (2 * p) * 64;
        *(float4*)pe       = make_float4(a[0].x, a[1].x, a[2].x, a[3].x);
        *(float4*)(pe + 4) = make_float4(a[4].x, a[5].x, a[6].x, a[7].x);
        float* po = Sd + (2 * p + 1) * 64;
        *(float4*)po       = make_float4(a[0].y, a[1].y, a[2].y, a[3].y);
        *(float4*)(po + 4) = make_float4(a[4].y, a[5].y, a[6].y, a[7].y);
    }
}

// --------------------- per-mode complex mix, both paths ---------------------
__global__ __launch_bounds__(256) void k_mix() {
    extern __shared__ float sm[];
    float* Ss  = sm;             // [64 slabs][132]
    float* Wre = sm + 64 * 132;
    float* Wim = Wre + 4096;
    int which = blockIdx.x >> 6;
    const float* wt  = which ? g_w2t : g_w1t;
    const float* Ssrc = which ? g_S2 : g_S;
    float* Tdst = which ? g_T2 : g_T;
    int t = threadIdx.x;
    int k = blockIdx.y;
    int s0 = (blockIdx.x & 63) * 64;

    for (int i = t; i < 2048; i += 256) {
        int s = i >> 5, q = (i & 31) * 4;
        float4 v = *(const float4*)(Ssrc + (size_t)(s0 + s) * 4096u + (size_t)k * 128u + q);
        *(float4*)(Ss + s * 132 + q) = v;
    }
    for (int i = t; i < 1024; i += 256) {
        ((float4*)Wre)[i] = *(const float4*)(wt + (size_t)k * 4096u + i * 4);
        ((float4*)Wim)[i] = *(const float4*)(wt + 131072u + (size_t)k * 4096u + i * 4);
    }
    __syncthreads();
    int tx = t & 15, ty = t >> 4;
    u64 ar[4][2] = {}, ai[4][2] = {};
#pragma unroll 4
    for (int c = 0; c < 64; c++) {
        ulonglong2 wr = *(const ulonglong2*)(Wre + c * 64 + tx * 4);
        ulonglong2 wi = *(const ulonglong2*)(Wim + c * 64 + tx * 4);
#pragma unroll
        for (int i = 0; i < 4; i++) {
            float srv = Ss[(ty * 4 + i) * 132 + c];
            float siv = Ss[(ty * 4 + i) * 132 + 64 + c];
            u64 sr2 = pack2(srv, srv), si2 = pack2(siv, siv), ns2 = pack2(-siv, -siv);
            fma2(ar[i][0], sr2, wr.x); fma2(ar[i][0], ns2, wi.x);
            fma2(ar[i][1], sr2, wr.y); fma2(ar[i][1], ns2, wi.y);
            fma2(ai[i][0], sr2, wi.x); fma2(ai[i][0], si2, wr.x);
            fma2(ai[i][1], sr2, wi.y); fma2(ai[i][1], si2, wr.y);
        }
    }
#pragma unroll
    for (int i = 0; i < 4; i++) {
        float* Tp = Tdst + (size_t)(s0 + ty * 4 + i) * 4096u + (size_t)(2 * k) * 64u + tx * 4;
        float2 r0 = unpk(ar[i][0]), r1 = unpk(ar[i][1]);
        float2 m0 = unpk(ai[i][0]), m1 = unpk(ai[i][1]);
        *(float4*)Tp        = make_float4(r0.x, r0.y, r1.x, r1.y);
        *(float4*)(Tp + 64) = make_float4(m0.x, m0.y, m1.x, m1.y);
    }
}

// --------------------- inverse DFT GEMM (R15 + src param) -------------------
__global__ __launch_bounds__(256) void k_inv(const float* __restrict__ Tsrc, int xpath) {
    extern __shared__ float sm[];
    float* Ts = sm;
    float* Cs = sm + 4096;
    int t = threadIdx.x;
    int slab = blockIdx.x;
    {
        const float4* tsrc = (const float4*)(Tsrc + (size_t)slab * 4096u);
        for (int i = t; i < 1024; i += 256) ((float4*)Ts)[i] = tsrc[i];
    }
    int tx = t & 7, ty = t >> 3;
    size_t xbase = (size_t)(slab >> 8) * 4194304u + (size_t)(slab & 255) * 64u;

    for (int ch = 0; ch < 2; ch++) {
        for (int i = t; i < 8192; i += 256)
            Cs[(i >> 6) * 65 + (i & 63)] = g_Cit[ch * 8192 + i];
        __syncthreads();
        int n0 = ty * 4;
        u64 acc[4][4] = {};
#pragma unroll 2
        for (int kr = 0; kr < 64; kr++) {
            ulonglong2 t0 = *(const ulonglong2*)(Ts + kr * 64 + tx * 4);
            ulonglong2 t1 = *(const ulonglong2*)(Ts + kr * 64 + 32 + tx * 4);
#pragma unroll
            for (int i = 0; i < 4; i++) {
                float cv = Cs[(n0 + i) * 65 + kr];
                u64 c2 = pack2(cv, cv);
                fma2(acc[i][0], c2, t0.x); fma2(acc[i][1], c2, t0.y);
                fma2(acc[i][2], c2, t1.x); fma2(acc[i][3], c2, t1.y);
            }
        }
        int nb = ch * 128 + n0;
        if (!xpath) {
            float* dst = g_Z + (size_t)slab * 16384u;
#pragma unroll
            for (int i = 0; i < 4; i++) {
                float* p = dst + (size_t)(nb + i) * 64u + tx * 4;
                float2 a0 = unpk(acc[i][0]), a1 = unpk(acc[i][1]);
                float2 a2 = unpk(acc[i][2]), a3 = unpk(acc[i][3]);
                *(float4*)p        = make_float4(a0.x, a0.y, a1.x, a1.y);
                *(float4*)(p + 32) = make_float4(a2.x, a2.y, a3.x, a3.y);
            }
        } else {
#pragma unroll
            for (int i = 0; i < 4; i++) {
                float* p = g_Z + xbase + (size_t)(nb + i) * 16384u + tx * 4;
                float4 v0 = *(float4*)p, v1 = *(float4*)(p + 32);
                float2 a0 = unpk(acc[i][0]), a1 = unpk(acc[i][1]);
                float2 a2 = unpk(acc[i][2]), a3 = unpk(acc[i][3]);
                v0.x += a0.x; v0.y += a0.y; v0.z += a1.x; v0.w += a1.y;
                v1.x += a2.x; v1.y += a2.y; v1.z += a3.x; v1.w += a3.y;
                *(float4*)p = v0; *(float4*)(p + 32) = v1;
            }
        }
        __syncthreads();
    }
}

// --------------------- FF + LN: transposed z/H staging ----------------------
// smem (floats): W1s 16384 | W2s 16384 | Zt[64c][68] 4352 (reused as P[64o][68])
//                | Ht[256j][68] 17408 | b1s 256 | b2s,gs,bs,mus,rss 5x64
#define OFF_W2 16384
#define OFF_ZT 32768
#define OFF_HT 37120
#define OFF_B1 54528
#define OFF_B2 54784
#define OFF_G  54848
#define OFF_B  54912
#define OFF_MU 54976
#define OFF_RS 55040
#define FF_SMEM (55104 * 4)

__global__ __launch_bounds__(256) void k_ff(
    const float* __restrict__ w1, const float* __restrict__ b1,
    const float* __restrict__ w2, const float* __restrict__ b2,
    const float* __restrict__ lg, const float* __restrict__ lb,
    float* __restrict__ out)
{
    extern __shared__ float sm[];
    float* W1s = sm;
    float* W2s = sm + OFF_W2;
    float* Zt  = sm + OFF_ZT;    // z transposed [c][row]; later P [o][row]
    float* Ht  = sm + OFF_HT;    // H transposed [j][row]
    float* b1s = sm + OFF_B1;
    float* b2s = sm + OFF_B2;
    float* gs  = sm + OFF_G;
    float* bs  = sm + OFF_B;
    float* mus = sm + OFF_MU;
    float* rss = sm + OFF_RS;
    int t = threadIdx.x;

    for (int i = t; i < 4096; i += 256) {
        ((float4*)W1s)[i] = ((const float4*)w1)[i];
        ((float4*)W2s)[i] = ((const float4*)w2)[i];
    }
    b1s[t] = b1[t];
    if (t < 64) { b2s[t] = b2[t]; gs[t] = lg[t]; bs[t] = lb[t]; }
    __syncthreads();

    int txs = t & 31, tys = t >> 5;          // stage1: j-words x row-groups
    int rg = t & 7, og = (t >> 3) & 7, q = t >> 6;  // stage2

    for (int g = 0; g < 8; g++) {
        size_t r0 = (size_t)blockIdx.x * 512u + (size_t)g * 64u;

        // ---- stage z transposed ------------------------------------------
        {
            const float4* zsrc = (const float4*)(g_Z + r0 * 64u);
            for (int i = t; i < 1024; i += 256) {
                int row = i >> 4, c4 = (i & 15) * 4;
                float4 v = zsrc[i];
                Zt[(c4 + 0) * 68 + row] = v.x;
                Zt[(c4 + 1) * 68 + row] = v.y;
                Zt[(c4 + 2) * 68 + row] = v.z;
                Zt[(c4 + 3) * 68 + row] = v.w;
            }
        }
        __syncthreads();

        // ---- stage 1: H = relu(Z @ W1 + b1) -> Ht[j][row] ----------------
        {
            u64 acc[8][4];
            {
                ulonglong2 bA = *(const ulonglong2*)(b1s + txs * 4);
                ulonglong2 bB = *(const ulonglong2*)(b1s + 128 + txs * 4);
#pragma unroll
                for (int i = 0; i < 8; i++) {
                    acc[i][0] = bA.x; acc[i][1] = bA.y;
                    acc[i][2] = bB.x; acc[i][3] = bB.y;
                }
            }
#pragma unroll 4
            for (int c = 0; c < 64; c++) {
                const float* zc = Zt + c * 68 + tys * 8;
                float4 z0 = *(const float4*)zc, z1 = *(const float4*)(zc + 4);
                float zr[8] = {z0.x, z0.y, z0.z, z0.w, z1.x, z1.y, z1.z, z1.w};
                ulonglong2 wA = *(const ulonglong2*)(W1s + c * 256 + txs * 4);
                ulonglong2 wB = *(const ulonglong2*)(W1s + c * 256 + 128 + txs * 4);
#pragma unroll
                for (int i = 0; i < 8; i++) {
                    u64 z2 = pack2(zr[i], zr[i]);
                    fma2(acc[i][0], z2, wA.x); fma2(acc[i][1], z2, wA.y);
                    fma2(acc[i][2], z2, wB.x); fma2(acc[i][3], z2, wB.y);
                }
            }
            // write Ht transposed (j rows of 8 row-values)
#pragma unroll
            for (int jj = 0; jj < 4; jj++) {
                int w = jj >> 1;
                float va[8];
#pragma unroll
                for (int i = 0; i < 8; i++) {
                    float2 p = unpk(acc[i][w]);
                    va[i] = fmaxf((jj & 1) ? p.y : p.x, 0.f);
                }
                float* hp = Ht + (txs * 4 + jj) * 68 + tys * 8;
                *(float4*)hp       = make_float4(va[0], va[1], va[2], va[3]);
                *(float4*)(hp + 4) = make_float4(va[4], va[5], va[6], va[7]);
#pragma unroll
                for (int i = 0; i < 8; i++) {
                    float2 p = unpk(acc[i][w + 2]);
                    va[i] = fmaxf((jj & 1) ? p.y : p.x, 0.f);
                }
                float* hq = Ht + (128 + txs * 4 + jj) * 68 + tys * 8;
                *(float4*)hq       = make_float4(va[0], va[1], va[2], va[3]);
                *(float4*)(hq + 4) = make_float4(va[4], va[5], va[6], va[7]);
            }
        }
        __syncthreads();   // z consumed -> Zt reusable as P

        // ---- stage 2: Y = H @ W2 + b2, rows rg*8..+8, 4-way k-split -------
        u64 acc2[8][4] = {};
        {
            int j0 = q * 64;
#pragma unroll 4
            for (int jj = 0; jj < 64; jj++) {
                int j = j0 + jj;
                const float* hc = Ht + j * 68 + rg * 8;
                float4 h0 = *(const float4*)hc, h1 = *(const float4*)(hc + 4);
                float hr[8] = {h0.x, h0.y, h0.z, h0.w, h1.x, h1.y, h1.z, h1.w};
                ulonglong2 wA = *(const ulonglong2*)(W2s + j * 64 + og * 4);
                ulonglong2 wB = *(const ulonglong2*)(W2s + j * 64 + 32 + og * 4);
#pragma unroll
                for (int i = 0; i < 8; i++) {
                    u64 h2 = pack2(hr[i], hr[i]);
                    fma2(acc2[i][0], h2, wA.x); fma2(acc2[i][1], h2, wA.y);
                    fma2(acc2[i][2], h2, wB.x); fma2(acc2[i][3], h2, wB.y);
                }
            }
        }
        // serialized partial reduce into P[o][row] (= Zt)
        for (int s = 1; s <= 3; s++) {
            if (q == s) {
#pragma unroll
                for (int part = 0; part < 2; part++) {
#pragma unroll
                    for (int k = 0; k < 4; k++) {
                        int w = part * 2 + (k >> 1);
                        int o = part * 32 + og * 4 + k;
                        float va[8];
#pragma unroll
                        for (int i = 0; i < 8; i++) {
                            float2 p = unpk(acc2[i][w]);
                            va[i] = (k & 1) ? p.y : p.x;
                        }
                        float* pp = Zt + o * 68 + rg * 8;
                        float4 v0 = make_float4(va[0], va[1], va[2], va[3]);
                        float4 v1 = make_float4(va[4], va[5], va[6], va[7]);
                        if (s > 1) {
                            float4 e0 = *(float4*)pp, e1 = *(float4*)(pp + 4);
                            v0.x += e0.x; v0.y += e0.y; v0.z += e0.z; v0.w += e0.w;
                            v1.x += e1.x; v1.y += e1.y; v1.z += e1.z; v1.w += e1.w;
                        }
                        *(float4*)pp = v0; *(float4*)(pp + 4) = v1;
                    }
                }
            }
            __syncthreads();
        }
        if (q == 0) {
#pragma unroll
            for (int part = 0; part < 2; part++) {
#pragma unroll
                for (int k = 0; k < 4; k++) {
                    int w = part * 2 + (k >> 1);
                    int o = part * 32 + og * 4 + k;
                    float bv = b2s[o];
                    float va[8];
#pragma unroll
                    for (int i = 0; i < 8; i++) {
                        float2 p = unpk(acc2[i][w]);
                        va[i] = ((k & 1) ? p.y : p.x) + bv;
                    }
                    float* pp = Zt + o * 68 + rg * 8;
                    float4 e0 = *(float4*)pp, e1 = *(float4*)(pp + 4);
                    e0.x += va[0]; e0.y += va[1]; e0.z += va[2]; e0.w += va[3];
                    e1.x += va[4]; e1.y += va[5]; e1.z += va[6]; e1.w += va[7];
                    *(float4*)pp = e0; *(float4*)(pp + 4) = e1;
                }
            }
        }
        __syncthreads();

        // ---- LayerNorm (y in P[o][row]) -----------------------------------
        if (t < 64) {
            float s = 0.f, s2 = 0.f;
#pragma unroll 8
            for (int o = 0; o < 64; o++) {
                float v = Zt[o * 68 + t];
                s += v; s2 += v * v;
            }
            float mu = s * 0.015625f;
            float var = s2 * 0.015625f - mu * mu;
            mus[t] = mu; rss[t] = rsqrtf(var + 1e-5f);
        }
        __syncthreads();
        {
            int row = t >> 2, cg = (t & 3) * 16;
            float mu = mus[row], rs = rss[row];
            float* op = out + (r0 + (size_t)row) * 64u;
#pragma unroll
            for (int kk = 0; kk < 4; kk++) {
                int c = cg + kk * 4;
                float4 o4;
                o4.x = (Zt[(c + 0) * 68 + row] - mu) * rs * gs[c + 0] + bs[c + 0];
                o4.y = (Zt[(c + 1) * 68 + row] - mu) * rs * gs[c + 1] + bs[c + 1];
                o4.z = (Zt[(c + 2) * 68 + row] - mu) * rs * gs[c + 2] + bs[c + 2];
                o4.w = (Zt[(c + 3) * 68 + row] - mu) * rs * gs[c + 3] + bs[c + 3];
                *(float4*)(op + c) = o4;
            }
        }
        __syncthreads();
    }
}

// ----------------------------- launch ---------------------------------------
extern "C" void kernel_launch(void* const* d_in, const int* in_sizes, int n_in,
                              void* d_out, int out_size) {
    (void)in_sizes; (void)n_in; (void)out_size;
    const float* x    = (const float*)d_in[0];
    const float* w1re = (const float*)d_in[1];
    const float* w1im = (const float*)d_in[2];
    const float* w2re = (const float*)d_in[3];
    const float* w2im = (const float*)d_in[4];
    const float* ffw1 = (const float*)d_in[5];
    const float* ffb1 = (const float*)d_in[6];
    const float* ffw2 = (const float*)d_in[7];
    const float* ffb2 = (const float*)d_in[8];
    const float* lng  = (const float*)d_in[9];
    const float* lnb  = (const float*)d_in[10];
    float* out = (float*)d_out;

    cudaFuncSetAttribute(k_fwd, cudaFuncAttributeMaxDynamicSharedMemorySize, 40960);
    cudaFuncSetAttribute(k_mix, cudaFuncAttributeMaxDynamicSharedMemorySize, 66560);
    cudaFuncSetAttribute(k_inv, cudaFuncAttributeMaxDynamicSharedMemorySize, 49664);
    cudaFuncSetAttribute(k_ff,  cudaFuncAttributeMaxDynamicSharedMemorySize, FF_SMEM);

    k_basis<<<64, 256>>>();
    k_wt<<<512, 256>>>(w1re, w1im, w2re, w2im);

    float* dT;  cudaGetSymbolAddress((void**)&dT,  g_T);
    float* dT2; cudaGetSymbolAddress((void**)&dT2, g_T2);

    k_fwd<<<2048, 256, 40960>>>(x);                 // both paths
    k_mix<<<dim3(128, 32), 256, 66560>>>();         // both paths
    k_inv<<<4096, 256, 49664>>>(dT, 0);             // y-path writes Z
    k_inv<<<4096, 256, 49664>>>(dT2, 1);            // x-path accumulates
    k_ff<<<2048, 256, FF_SMEM>>>(ffw1, ffb1, ffw2, ffb2, lng, lnb, out);
}